// round 1
// baseline (speedup 1.0000x reference)
#include <cuda_runtime.h>
#include <math.h>

// REDE_INFER: acc = sum_{s=1..7} M^s * (cumulative 1/decays), then / sqrt(7).
// One CTA per 64x64 matrix. We iterate the TRANSPOSED chain:
//   Q_1 = M^T,  Q_{s+1} = (M^T) @ Q_s * invdec[s]   (Q_s = (M^s)^T, scaled)
// so that the A-operand vector loads read rows of M (Mt[i][k] = M[k][i] ->
// float4 from Mn[k*64+i0]) and the B-operand vector loads read rows of Q.
// accT accumulates in registers; final transpose staged through smem once.

struct DecayParams { float inv[8]; };  // inv[1..6] = 1/decays, inv[7] = 1/sqrt(7)

__global__ void __launch_bounds__(128, 4)
rede_kernel(const float* __restrict__ G, float* __restrict__ O, DecayParams dp)
{
    __shared__ float Mn[64 * 64];      // M row-major
    __shared__ float Q[2][64 * 64];    // Q_s row-major, double buffered

    const int m = blockIdx.x;
    const float* Gm = G + (size_t)m * 4096;
    float*       Om = O + (size_t)m * 4096;

    const int tid = threadIdx.x;           // 128 threads
    const int i0  = (tid >> 3) * 4;         // Q-row block  (4 rows)
    const int j0  = (tid & 7) * 8;          // Q-col block  (8 cols)

    // ---- load M (coalesced float4) + build Q_1 = M^T ----
    #pragma unroll
    for (int w = 0; w < 8; w++) {
        int f = tid + w * 128;                       // float4 index, 0..1023
        float4 v = reinterpret_cast<const float4*>(Gm)[f];
        reinterpret_cast<float4*>(Mn)[f] = v;
        int e = f * 4;
        int r = e >> 6, c = e & 63;
        Q[0][(c + 0) * 64 + r] = v.x;
        Q[0][(c + 1) * 64 + r] = v.y;
        Q[0][(c + 2) * 64 + r] = v.z;
        Q[0][(c + 3) * 64 + r] = v.w;
    }
    __syncthreads();

    // ---- accT init = Q_1 tile = Mt[i0..][j0..] = M[j0+j][i0+i] ----
    float accT[4][8];
    #pragma unroll
    for (int j = 0; j < 8; j++) {
        float4 col = *reinterpret_cast<const float4*>(Mn + (j0 + j) * 64 + i0);
        accT[0][j] = col.x; accT[1][j] = col.y;
        accT[2][j] = col.z; accT[3][j] = col.w;
    }

    int cur = 0;
    #pragma unroll 1
    for (int step = 1; step < 7; step++) {
        const float* Qc = Q[cur];
        float*       Qn = Q[cur ^ 1];

        float c[4][8];
        #pragma unroll
        for (int i = 0; i < 4; i++)
            #pragma unroll
            for (int j = 0; j < 8; j++) c[i][j] = 0.0f;

        // Qn[i][j] = sum_k Mn[k*64+i] * Qc[k*64+j]
        #pragma unroll 8
        for (int k = 0; k < 64; k++) {
            float4 a  = *reinterpret_cast<const float4*>(Mn + k * 64 + i0);
            float4 b0 = *reinterpret_cast<const float4*>(Qc + k * 64 + j0);
            float4 b1 = *reinterpret_cast<const float4*>(Qc + k * 64 + j0 + 4);
            float av[4] = {a.x, a.y, a.z, a.w};
            float bv[8] = {b0.x, b0.y, b0.z, b0.w, b1.x, b1.y, b1.z, b1.w};
            #pragma unroll
            for (int i = 0; i < 4; i++)
                #pragma unroll
                for (int j = 0; j < 8; j++)
                    c[i][j] = fmaf(av[i], bv[j], c[i][j]);
        }

        const float s = dp.inv[step];
        #pragma unroll
        for (int i = 0; i < 4; i++) {
            #pragma unroll
            for (int j = 0; j < 8; j++) {
                c[i][j] *= s;
                accT[i][j] += c[i][j];
            }
            float4 v0 = make_float4(c[i][0], c[i][1], c[i][2], c[i][3]);
            float4 v1 = make_float4(c[i][4], c[i][5], c[i][6], c[i][7]);
            *reinterpret_cast<float4*>(Qn + (i0 + i) * 64 + j0)     = v0;
            *reinterpret_cast<float4*>(Qn + (i0 + i) * 64 + j0 + 4) = v1;
        }
        __syncthreads();
        cur ^= 1;
    }

    // ---- transpose accT -> acc via smem, scaled by 1/sqrt(7), store ----
    const float fs = dp.inv[7];
    float* Sm = Mn;  // M no longer needed; last step's reads fenced by its sync
    #pragma unroll
    for (int j = 0; j < 8; j++) {
        float4 v = make_float4(accT[0][j] * fs, accT[1][j] * fs,
                               accT[2][j] * fs, accT[3][j] * fs);
        // Sm[r*64 + c] = acc[r][c] = accT[c][r]; here r = j0+j, c block = i0..i0+3
        *reinterpret_cast<float4*>(Sm + (j0 + j) * 64 + i0) = v;
    }
    __syncthreads();
    #pragma unroll
    for (int w = 0; w < 8; w++) {
        int f = tid + w * 128;
        reinterpret_cast<float4*>(Om)[f] = reinterpret_cast<const float4*>(Sm)[f];
    }
}

extern "C" void kernel_launch(void* const* d_in, const int* in_sizes, int n_in,
                              void* d_out, int out_size)
{
    const float* M = (const float*)d_in[0];
    float* out = (float*)d_out;
    int nmat = in_sizes[0] / 4096;

    // Exact integer variances from the reference _D_PARMS at R=64.
    static const double V[7] = {
        1.0, 64.0, 4104.0, 263696.0, 17021060.0, 1104218816.0, 72260728960.0
    };
    DecayParams dp;
    dp.inv[0] = 1.0f;
    for (int s = 1; s < 7; s++)
        dp.inv[s] = (float)(1.0 / sqrt(V[s] / V[s - 1]));
    dp.inv[7] = (float)(1.0 / sqrt(7.0));

    rede_kernel<<<nmat, 128>>>(M, out, dp);
}

// round 2
// speedup vs baseline: 2.5301x; 2.5301x over previous
#include <cuda_runtime.h>
#include <math.h>

typedef unsigned long long u64;

// acc = (1/sqrt(7)) * sum_{p=1..7} M^p / sqrt(V_p)   (V_1 = 1)
// Paterson-Stockmeyer with 4 GEMMs on unit-variance intermediates:
//   W2 = k2*(M*M), W4 = k4*(W2*W2), W6 = k6*(W4*W2)
//   E  = I + c3*W2 + c5*W4 + c7*W6
//   acc = fs * (W2 + W4 + W6 + M*E)
struct Coefs { float k2, k4, k6, c3, c5, c7, fs; };

__device__ __forceinline__ u64 pk(float lo, float hi) {
    u64 r; asm("mov.b64 %0,{%1,%2};" : "=l"(r) : "f"(lo), "f"(hi)); return r;
}
__device__ __forceinline__ float2 upk(u64 v) {
    float2 r; asm("mov.b64 {%0,%1},%2;" : "=f"(r.x), "=f"(r.y) : "l"(v)); return r;
}
__device__ __forceinline__ u64 ffma2(u64 a, u64 b, u64 c) {
    u64 d; asm("fma.rn.f32x2 %0,%1,%2,%3;" : "=l"(d) : "l"(a), "l"(b), "l"(c)); return d;
}

// Swizzled index for transposed-layout buffers (kills transpose-store conflicts).
__device__ __forceinline__ int swz(int row, int col) {
    return row * 64 + (col ^ (((row >> 3) & 7) << 2));
}

// 8x8 tile (i0,j0) of D = A*B. At = A in column-major (i.e. A^T row-major),
// stored SWIZZLED. B row-major unswizzled. Result scaled by s into out[8][8].
// c packing: pair lanes along i (natural from float4 A loads).
__device__ __forceinline__ void gemm_tile(const float* __restrict__ At,
                                          const float* __restrict__ B,
                                          int i0, int j0, float s,
                                          float out[8][8])
{
    u64 c[4][8];
    #pragma unroll
    for (int i = 0; i < 4; i++)
        #pragma unroll
        for (int j = 0; j < 8; j++) c[i][j] = 0ull;

    #pragma unroll 8
    for (int k = 0; k < 64; k++) {
        float4 a0 = *(const float4*)(At + swz(k, i0));
        float4 a1 = *(const float4*)(At + swz(k, i0 + 4));
        float4 b0 = *(const float4*)(B + k * 64 + j0);
        float4 b1 = *(const float4*)(B + k * 64 + j0 + 4);
        u64 a2[4];
        a2[0] = pk(a0.x, a0.y); a2[1] = pk(a0.z, a0.w);
        a2[2] = pk(a1.x, a1.y); a2[3] = pk(a1.z, a1.w);
        float bv[8] = {b0.x, b0.y, b0.z, b0.w, b1.x, b1.y, b1.z, b1.w};
        #pragma unroll
        for (int j = 0; j < 8; j++) {
            u64 bd = pk(bv[j], bv[j]);
            #pragma unroll
            for (int i = 0; i < 4; i++) c[i][j] = ffma2(a2[i], bd, c[i][j]);
        }
    }
    #pragma unroll
    for (int i2 = 0; i2 < 4; i2++)
        #pragma unroll
        for (int j = 0; j < 8; j++) {
            float2 v = upk(c[i2][j]);
            out[2 * i2][j]     = v.x * s;
            out[2 * i2 + 1][j] = v.y * s;
        }
}

__device__ __forceinline__ void store_rm(float* dst, int i0, int j0,
                                         const float t[8][8]) {
    #pragma unroll
    for (int i = 0; i < 8; i++) {
        *(float4*)(dst + (i0 + i) * 64 + j0) =
            make_float4(t[i][0], t[i][1], t[i][2], t[i][3]);
        *(float4*)(dst + (i0 + i) * 64 + j0 + 4) =
            make_float4(t[i][4], t[i][5], t[i][6], t[i][7]);
    }
}
// transposed (swizzled) store: dst[swz(j, i)] = t[i][j]
__device__ __forceinline__ void store_tr(float* dst, int i0, int j0,
                                         const float t[8][8]) {
    #pragma unroll
    for (int j = 0; j < 8; j++) {
        *(float4*)(dst + swz(j0 + j, i0)) =
            make_float4(t[0][j], t[1][j], t[2][j], t[3][j]);
        *(float4*)(dst + swz(j0 + j, i0 + 4)) =
            make_float4(t[4][j], t[5][j], t[6][j], t[7][j]);
    }
}

__global__ void __launch_bounds__(64, 4)
rede_kernel(const float* __restrict__ G, float* __restrict__ O, Coefs cf)
{
    __shared__ float b0s[4096];  // Mt (swizzled), lives whole kernel
    __shared__ float b1s[4096];  // Ms -> W2s -> Es        (row-major)
    __shared__ float b2s[4096];  // W2t -> W4t (swizzled) -> Ss (row-major)

    const int m = blockIdx.x;
    const float* Gm = G + (size_t)m * 4096;
    float* Om = O + (size_t)m * 4096;
    const int tid = threadIdx.x;          // 64 threads
    const int i0 = (tid >> 3) * 8;
    const int j0 = (tid & 7) * 8;

    // ---- load M: Ms (row-major, b1s) + Mt (swizzled transposed, b0s) ----
    #pragma unroll
    for (int w = 0; w < 16; w++) {
        int f = tid + w * 64;                       // float4 index 0..1023
        float4 v = ((const float4*)Gm)[f];
        ((float4*)b1s)[f] = v;
        int e = f * 4; int r = e >> 6, c = e & 63;  // M[r][c..c+3]
        b0s[swz(c + 0, r)] = v.x;
        b0s[swz(c + 1, r)] = v.y;
        b0s[swz(c + 2, r)] = v.z;
        b0s[swz(c + 3, r)] = v.w;
    }
    __syncthreads();

    float t[8][8];

    // ---- W2 = k2 * M*M ----
    gemm_tile(b0s, b1s, i0, j0, cf.k2, t);
    __syncthreads();                 // all reads of Ms done before overwrite
    store_rm(b1s, i0, j0, t);        // W2s
    store_tr(b2s, i0, j0, t);        // W2t
    __syncthreads();

    // ---- W4 = k4 * W2*W2 ----
    gemm_tile(b2s, b1s, i0, j0, cf.k4, t);
    __syncthreads();                 // reads of W2t done
    store_tr(b2s, i0, j0, t);        // W4t
    __syncthreads();

    // ---- W6 = k6 * W4*W2 (stays in regs) ----
    gemm_tile(b2s, b1s, i0, j0, cf.k6, t);   // t = W6 tile

    // ---- E = I + c3*W2 + c5*W4 + c7*W6 ; S = W2 + W4 + W6 ----
    float w4a[8][8];
    #pragma unroll
    for (int j = 0; j < 8; j++) {   // W4 at (i0+i, j0+j) from swizzled W4t
        float4 va = *(const float4*)(b2s + swz(j0 + j, i0));
        float4 vb = *(const float4*)(b2s + swz(j0 + j, i0 + 4));
        w4a[0][j] = va.x; w4a[1][j] = va.y; w4a[2][j] = va.z; w4a[3][j] = va.w;
        w4a[4][j] = vb.x; w4a[5][j] = vb.y; w4a[6][j] = vb.z; w4a[7][j] = vb.w;
    }
    float e[8][8];
    #pragma unroll
    for (int i = 0; i < 8; i++) {
        float4 wa = *(const float4*)(b1s + (i0 + i) * 64 + j0);
        float4 wb = *(const float4*)(b1s + (i0 + i) * 64 + j0 + 4);
        float w2[8] = {wa.x, wa.y, wa.z, wa.w, wb.x, wb.y, wb.z, wb.w};
        #pragma unroll
        for (int j = 0; j < 8; j++) {
            float w4 = w4a[i][j];
            float w6 = t[i][j];
            float dg = ((i0 + i) == (j0 + j)) ? 1.0f : 0.0f;
            e[i][j] = dg + cf.c3 * w2[j] + cf.c5 * w4 + cf.c7 * w6;
            t[i][j] = w2[j] + w4 + w6;        // S overwrites t
        }
    }
    __syncthreads();                 // all reads of W2s/W4t complete
    store_rm(b1s, i0, j0, e);        // Es
    store_rm(b2s, i0, j0, t);        // Ss
    __syncthreads();

    // ---- F = M*E ; out = fs * (F + S) ----
    float f_[8][8];
    gemm_tile(b0s, b1s, i0, j0, 1.0f, f_);
    #pragma unroll
    for (int i = 0; i < 8; i++) {
        float4 sa = *(const float4*)(b2s + (i0 + i) * 64 + j0);
        float4 sb = *(const float4*)(b2s + (i0 + i) * 64 + j0 + 4);
        float sv[8] = {sa.x, sa.y, sa.z, sa.w, sb.x, sb.y, sb.z, sb.w};
        float4 o0 = make_float4(cf.fs * (f_[i][0] + sv[0]),
                                cf.fs * (f_[i][1] + sv[1]),
                                cf.fs * (f_[i][2] + sv[2]),
                                cf.fs * (f_[i][3] + sv[3]));
        float4 o1 = make_float4(cf.fs * (f_[i][4] + sv[4]),
                                cf.fs * (f_[i][5] + sv[5]),
                                cf.fs * (f_[i][6] + sv[6]),
                                cf.fs * (f_[i][7] + sv[7]));
        *(float4*)(Om + (i0 + i) * 64 + j0)     = o0;
        *(float4*)(Om + (i0 + i) * 64 + j0 + 4) = o1;
    }
}

extern "C" void kernel_launch(void* const* d_in, const int* in_sizes, int n_in,
                              void* d_out, int out_size)
{
    const float* M = (const float*)d_in[0];
    float* out = (float*)d_out;
    int nmat = in_sizes[0] / 4096;

    // Exact variances V_p of M^p entries at R=64 (from _D_PARMS), V_1 = 1.
    const double C2 = sqrt(64.0);
    const double C3 = sqrt(4104.0);
    const double C4 = sqrt(263696.0);
    const double C5 = sqrt(17021060.0);
    const double C6 = sqrt(1104218816.0);
    const double C7 = sqrt(72260728960.0);

    Coefs cf;
    cf.k2 = (float)(1.0 / C2);
    cf.k4 = (float)((C2 * C2) / C4);
    cf.k6 = (float)((C4 * C2) / C6);
    cf.c3 = (float)(C2 / C3);
    cf.c5 = (float)(C4 / C5);
    cf.c7 = (float)(C6 / C7);
    cf.fs = (float)(1.0 / sqrt(7.0));

    rede_kernel<<<nmat, 64>>>(M, out, cf);
}

// round 4
// speedup vs baseline: 5.2723x; 2.0839x over previous
#include <cuda_runtime.h>
#include <cuda_bf16.h>
#include <math.h>
#include <stdint.h>

typedef uint32_t u32;

// acc = (1/sqrt(7)) * sum_{p=1..7} M^p / sqrt(V_p)
// Paterson-Stockmeyer, unit-variance intermediates:
//   W2 = k2*(M*M), W4 = k4*(W2*W2), W6 = k6*(W4*W2)
//   E  = I + c3*W2 + c5*W4 + c7*W6
//   out = fs * (W2 + W4 + W6 + M*E)
// Each GEMM: bf16 hi/lo split, D = Ah*Bh + Al*Bh + Ah*Bl (fp32 accum),
// via mma.sync.m16n8k16 (works on compute_103 non-'a' target).
struct Coefs { float k2, k4, k6, c3, c5, c7, fs; };

// smem: six 8KB bf16 [64x64] buffers, rows 128B, XOR-swizzled.
#define OFF_MH  0u
#define OFF_ML  8192u
#define OFF_W2H 16384u
#define OFF_W2L 24576u
#define OFF_XH  32768u   // W4 then E
#define OFF_XL  40960u
#define SMEM_TOTAL 49152

static __device__ __forceinline__ u32 s2u(const void* p) {
    u32 a;
    asm("{ .reg .u64 t; cvta.to.shared.u64 t, %1; cvt.u32.u64 %0, t; }"
        : "=r"(a) : "l"(p));
    return a;
}
static __device__ __forceinline__ void ldsm4(u32* r, u32 a) {
    asm volatile("ldmatrix.sync.aligned.m8n8.x4.shared.b16 {%0,%1,%2,%3},[%4];"
                 : "=r"(r[0]), "=r"(r[1]), "=r"(r[2]), "=r"(r[3]) : "r"(a));
}
static __device__ __forceinline__ void ldsm4t(u32* r, u32 a) {
    asm volatile("ldmatrix.sync.aligned.m8n8.x4.trans.shared.b16 {%0,%1,%2,%3},[%4];"
                 : "=r"(r[0]), "=r"(r[1]), "=r"(r[2]), "=r"(r[3]) : "r"(a));
}
static __device__ __forceinline__ void mma16816(float* c, const u32* a, const u32* b) {
    asm volatile(
        "mma.sync.aligned.m16n8k16.row.col.f32.bf16.bf16.f32 "
        "{%0,%1,%2,%3},{%4,%5,%6,%7},{%8,%9},{%0,%1,%2,%3};"
        : "+f"(c[0]), "+f"(c[1]), "+f"(c[2]), "+f"(c[3])
        : "r"(a[0]), "r"(a[1]), "r"(a[2]), "r"(a[3]), "r"(b[0]), "r"(b[1]));
}

// split two fp32 -> packed bf16x2 hi + bf16x2 lo
static __device__ __forceinline__ void split2(float x0, float x1, u32& H, u32& L) {
    __nv_bfloat16 h0 = __float2bfloat16_rn(x0);
    __nv_bfloat16 h1 = __float2bfloat16_rn(x1);
    float r0 = x0 - __bfloat162float(h0);
    float r1 = x1 - __bfloat162float(h1);
    __nv_bfloat162 hh = __halves2bfloat162(h0, h1);
    __nv_bfloat162 ll = __halves2bfloat162(__float2bfloat16_rn(r0),
                                           __float2bfloat16_rn(r1));
    H = *reinterpret_cast<u32*>(&hh);
    L = *reinterpret_cast<u32*>(&ll);
}

// D-slab GEMM: warp computes rows [warp*16, +16) of D = A*B (64x64),
// 3-pass split accumulated into acc[32] (8 n-tiles x 4 regs).
static __device__ __forceinline__ void gemm3(float acc[32], u32 sb,
                                             u32 ah_off, u32 al_off,
                                             u32 bh_off, u32 bl_off,
                                             int warp, int lane)
{
#pragma unroll
    for (int i = 0; i < 32; i++) acc[i] = 0.f;
    const int sub = lane >> 3, l7 = lane & 7;
    const int arow = warp * 16 + ((sub & 1) << 3) + l7;
    const u32 abase = (u32)arow * 128u;
    const u32 asw = (u32)((arow & 7) << 4);
#pragma unroll
    for (int ks = 0; ks < 4; ks++) {
        u32 ab = abase + (((u32)ks * 32u + (u32)((sub >> 1) << 4)) ^ asw);
        u32 ah[4], al[4];
        ldsm4(ah, sb + ah_off + ab);
        ldsm4(al, sb + al_off + ab);
        const int krow = ks * 16 + ((sub & 1) << 3) + l7;
        const u32 kbase = (u32)krow * 128u;
        const u32 ksw = (u32)((krow & 7) << 4);
        u32 bh[16], bl[16];
#pragma unroll
        for (int np = 0; np < 4; np++) {
            u32 bb = kbase + (((u32)np * 32u + (u32)((sub >> 1) << 4)) ^ ksw);
            ldsm4t(bh + np * 4, sb + bh_off + bb);
            ldsm4t(bl + np * 4, sb + bl_off + bb);
        }
#pragma unroll
        for (int nt = 0; nt < 8; nt++) {
            mma16816(acc + nt * 4, ah, bh + nt * 2);
            mma16816(acc + nt * 4, al, bh + nt * 2);
            mma16816(acc + nt * 4, ah, bl + nt * 2);
        }
    }
}

// store fragment x[32] (warp's 16x64 slab) as bf16 hi/lo into swizzled smem
static __device__ __forceinline__ void st_frag(char* sm, u32 hoff, u32 loff,
                                               const float* x, int warp, int lane)
{
    const int g = lane >> 2, tg = lane & 3;
#pragma unroll
    for (int nt = 0; nt < 8; nt++) {
#pragma unroll
        for (int h = 0; h < 2; h++) {
            int r = warp * 16 + g + h * 8;
            u32 cb = (u32)(nt * 16 + tg * 4);
            u32 off = (u32)r * 128u + (cb ^ (u32)((r & 7) << 4));
            u32 H, L;
            split2(x[nt * 4 + h * 2 + 0], x[nt * 4 + h * 2 + 1], H, L);
            *reinterpret_cast<u32*>(sm + hoff + off) = H;
            *reinterpret_cast<u32*>(sm + loff + off) = L;
        }
    }
}

__global__ void __launch_bounds__(128, 2)
rede_mma(const float* __restrict__ G, float* __restrict__ O, Coefs cf)
{
    extern __shared__ __align__(128) char sm[];
    const u32 sb = s2u(sm);
    const int tid = threadIdx.x;
    const int warp = tid >> 5, lane = tid & 31;

    const float* Gm = G + (size_t)blockIdx.x * 4096;
    float*       Om = O + (size_t)blockIdx.x * 4096;

    // ---- prologue: load M, split to bf16 hi/lo, store swizzled ----
    {
        const int row = tid >> 1;
        const int halfb = (tid & 1) * 64;          // byte offset of 32-elem half
        const float* src = Gm + row * 64 + (tid & 1) * 32;
#pragma unroll
        for (int j = 0; j < 4; j++) {              // 4 chunks of 8 floats
            float4 a = *reinterpret_cast<const float4*>(src + j * 8);
            float4 b = *reinterpret_cast<const float4*>(src + j * 8 + 4);
            u32 h0, l0, h1, l1, h2, l2, h3, l3;
            split2(a.x, a.y, h0, l0);
            split2(a.z, a.w, h1, l1);
            split2(b.x, b.y, h2, l2);
            split2(b.z, b.w, h3, l3);
            u32 cb = (u32)(halfb + j * 16);
            u32 off = (u32)row * 128u + (cb ^ (u32)((row & 7) << 4));
            *reinterpret_cast<uint4*>(sm + OFF_MH + off) = make_uint4(h0, h1, h2, h3);
            *reinterpret_cast<uint4*>(sm + OFF_ML + off) = make_uint4(l0, l1, l2, l3);
        }
    }
    __syncthreads();

    // fragment coordinates for S/E bookkeeping
    const int g = lane >> 2, tg = lane & 3;

    float S[32], E[32], acc[32];
#pragma unroll
    for (int nt = 0; nt < 8; nt++)
#pragma unroll
        for (int h = 0; h < 2; h++) {
            int r = warp * 16 + g + h * 8;
            int c = nt * 8 + tg * 2;
            S[nt * 4 + h * 2 + 0] = 0.f;
            S[nt * 4 + h * 2 + 1] = 0.f;
            E[nt * 4 + h * 2 + 0] = (r == c) ? 1.f : 0.f;
            E[nt * 4 + h * 2 + 1] = (r == c + 1) ? 1.f : 0.f;
        }

    // ---- G1: W2 = k2 * M*M ----
    gemm3(acc, sb, OFF_MH, OFF_ML, OFF_MH, OFF_ML, warp, lane);
#pragma unroll
    for (int i = 0; i < 32; i++) {
        float x = cf.k2 * acc[i];
        S[i] += x; E[i] += cf.c3 * x; acc[i] = x;
    }
    st_frag(sm, OFF_W2H, OFF_W2L, acc, warp, lane);
    __syncthreads();

    // ---- G2: W4 = k4 * W2*W2 ----
    gemm3(acc, sb, OFF_W2H, OFF_W2L, OFF_W2H, OFF_W2L, warp, lane);
#pragma unroll
    for (int i = 0; i < 32; i++) {
        float x = cf.k4 * acc[i];
        S[i] += x; E[i] += cf.c5 * x; acc[i] = x;
    }
    st_frag(sm, OFF_XH, OFF_XL, acc, warp, lane);
    __syncthreads();

    // ---- G3: W6 = k6 * W4*W2 ----
    gemm3(acc, sb, OFF_XH, OFF_XL, OFF_W2H, OFF_W2L, warp, lane);
#pragma unroll
    for (int i = 0; i < 32; i++) {
        float x = cf.k6 * acc[i];
        S[i] += x; E[i] += cf.c7 * x;
    }
    __syncthreads();                     // all G3 reads of X(=W4) done
    st_frag(sm, OFF_XH, OFF_XL, E, warp, lane);   // X <- E
    __syncthreads();

    // ---- G4: F = M*E ; out = fs*(F + S) ----
    gemm3(acc, sb, OFF_MH, OFF_ML, OFF_XH, OFF_XL, warp, lane);
#pragma unroll
    for (int nt = 0; nt < 8; nt++)
#pragma unroll
        for (int h = 0; h < 2; h++) {
            int r = warp * 16 + g + h * 8;
            int c = nt * 8 + tg * 2;
            float2 v;
            v.x = cf.fs * (acc[nt * 4 + h * 2 + 0] + S[nt * 4 + h * 2 + 0]);
            v.y = cf.fs * (acc[nt * 4 + h * 2 + 1] + S[nt * 4 + h * 2 + 1]);
            *reinterpret_cast<float2*>(Om + r * 64 + c) = v;
        }
}

extern "C" void kernel_launch(void* const* d_in, const int* in_sizes, int n_in,
                              void* d_out, int out_size)
{
    const float* M = (const float*)d_in[0];
    float* out = (float*)d_out;
    int nmat = in_sizes[0] / 4096;

    // Exact variances V_p of M^p entries at R=64 (from _D_PARMS), V_1 = 1.
    const double C2 = sqrt(64.0);
    const double C3 = sqrt(4104.0);
    const double C4 = sqrt(263696.0);
    const double C5 = sqrt(17021060.0);
    const double C6 = sqrt(1104218816.0);
    const double C7 = sqrt(72260728960.0);

    Coefs cf;
    cf.k2 = (float)(1.0 / C2);
    cf.k4 = (float)((C2 * C2) / C4);
    cf.k6 = (float)((C4 * C2) / C6);
    cf.c3 = (float)(C2 / C3);
    cf.c5 = (float)(C4 / C5);
    cf.c7 = (float)(C6 / C7);
    cf.fs = (float)(1.0 / sqrt(7.0));

    cudaFuncSetAttribute(rede_mma, cudaFuncAttributeMaxDynamicSharedMemorySize,
                         SMEM_TOTAL);
    rede_mma<<<nmat, 128, SMEM_TOTAL>>>(M, out, cf);
}

// round 5
// speedup vs baseline: 5.5423x; 1.0512x over previous
#include <cuda_runtime.h>
#include <cuda_bf16.h>
#include <math.h>
#include <stdint.h>

typedef uint32_t u32;

// acc = (1/sqrt(7)) * sum_{p=1..7} M^p / sqrt(V_p)
// Paterson-Stockmeyer, unit-variance intermediates:
//   W2 = k2*(M*M), W4 = k4*(W2*W2), W6 = k6*(W4*W2)
//   E  = I + c3*W2 + c5*W4 + c7*W6
//   out = fs * (W2 + W4 + W6 + M*E)
// GEMMs: bf16 hi/lo split, D = Ah*Bh + Al*Bh + Ah*Bl (fp32 accum), mma.m16n8k16.
// Warp tile 32x32 (2x2 warp grid), S reconstructed from smem readback.
struct Coefs { float k2, k4, k6, c3, c5, c7, fs; };

#define OFF_MH  0u
#define OFF_ML  8192u
#define OFF_W2H 16384u
#define OFF_W2L 24576u
#define OFF_XH  32768u   // W4 then E
#define OFF_XL  40960u
#define SMEM_TOTAL 49152

static __device__ __forceinline__ u32 s2u(const void* p) {
    u32 a;
    asm("{ .reg .u64 t; cvta.to.shared.u64 t, %1; cvt.u32.u64 %0, t; }"
        : "=r"(a) : "l"(p));
    return a;
}
static __device__ __forceinline__ void ldsm4(u32* r, u32 a) {
    asm volatile("ldmatrix.sync.aligned.m8n8.x4.shared.b16 {%0,%1,%2,%3},[%4];"
                 : "=r"(r[0]), "=r"(r[1]), "=r"(r[2]), "=r"(r[3]) : "r"(a));
}
static __device__ __forceinline__ void ldsm4t(u32* r, u32 a) {
    asm volatile("ldmatrix.sync.aligned.m8n8.x4.trans.shared.b16 {%0,%1,%2,%3},[%4];"
                 : "=r"(r[0]), "=r"(r[1]), "=r"(r[2]), "=r"(r[3]) : "r"(a));
}
static __device__ __forceinline__ void mma16816(float* c, const u32* a, const u32* b) {
    asm volatile(
        "mma.sync.aligned.m16n8k16.row.col.f32.bf16.bf16.f32 "
        "{%0,%1,%2,%3},{%4,%5,%6,%7},{%8,%9},{%0,%1,%2,%3};"
        : "+f"(c[0]), "+f"(c[1]), "+f"(c[2]), "+f"(c[3])
        : "r"(a[0]), "r"(a[1]), "r"(a[2]), "r"(a[3]), "r"(b[0]), "r"(b[1]));
}
static __device__ __forceinline__ void split2(float x0, float x1, u32& H, u32& L) {
    __nv_bfloat16 h0 = __float2bfloat16_rn(x0);
    __nv_bfloat16 h1 = __float2bfloat16_rn(x1);
    float r0 = x0 - __bfloat162float(h0);
    float r1 = x1 - __bfloat162float(h1);
    __nv_bfloat162 hh = __halves2bfloat162(h0, h1);
    __nv_bfloat162 ll = __halves2bfloat162(__float2bfloat16_rn(r0),
                                           __float2bfloat16_rn(r1));
    H = *reinterpret_cast<u32*>(&hh);
    L = *reinterpret_cast<u32*>(&ll);
}

// 3-pass split GEMM into acc[32]: warp computes D[RM..RM+32, CNB/2..+32].
static __device__ __forceinline__ void gemm3(float acc[32], u32 sb,
                                             u32 ahoff, u32 aloff,
                                             u32 bhoff, u32 bloff,
                                             int RM, int CNB, int lane)
{
#pragma unroll
    for (int i = 0; i < 32; i++) acc[i] = 0.f;
    const int sub = lane >> 3, l7 = lane & 7;
#pragma unroll
    for (int ks = 0; ks < 4; ks++) {
        u32 ah[8], al[8];
#pragma unroll
        for (int mt = 0; mt < 2; mt++) {
            int arow = RM + mt * 16 + ((sub & 1) << 3) + l7;
            u32 ab = (u32)arow * 128u +
                     (((u32)(ks * 32 + ((sub >> 1) << 4))) ^ (u32)((arow & 7) << 4));
            ldsm4(ah + mt * 4, sb + ahoff + ab);
            ldsm4(al + mt * 4, sb + aloff + ab);
        }
        const int krow = ks * 16 + ((sub & 1) << 3) + l7;
        const u32 kb = (u32)krow * 128u;
        const u32 ksw = (u32)((krow & 7) << 4);
        u32 bh[8], bl[8];
#pragma unroll
        for (int np = 0; np < 2; np++) {
            u32 bb = kb + (((u32)(CNB + np * 32 + ((sub >> 1) << 4))) ^ ksw);
            ldsm4t(bh + np * 4, sb + bhoff + bb);
            ldsm4t(bl + np * 4, sb + bloff + bb);
        }
#pragma unroll
        for (int mt = 0; mt < 2; mt++)
#pragma unroll
            for (int nt = 0; nt < 4; nt++) {
                float* c = acc + (mt * 4 + nt) * 4;
                mma16816(c, ah + mt * 4, bh + nt * 2);
                mma16816(c, al + mt * 4, bh + nt * 2);
                mma16816(c, ah + mt * 4, bl + nt * 2);
            }
    }
}

// store fragment (warp 32x32 tile) as bf16 hi/lo, swizzled
static __device__ __forceinline__ void st32(char* sm, u32 hoff, u32 loff,
                                            const float* x, int RM, int CNB, int lane)
{
    const int g = lane >> 2, tg = lane & 3;
#pragma unroll
    for (int mt = 0; mt < 2; mt++)
#pragma unroll
        for (int nt = 0; nt < 4; nt++)
#pragma unroll
            for (int h = 0; h < 2; h++) {
                int r = RM + mt * 16 + g + h * 8;
                u32 off = (u32)r * 128u +
                          (((u32)(CNB + nt * 16 + tg * 4)) ^ (u32)((r & 7) << 4));
                u32 H, L;
                int i = (mt * 4 + nt) * 4 + h * 2;
                split2(x[i], x[i + 1], H, L);
                *reinterpret_cast<u32*>(sm + hoff + off) = H;
                *reinterpret_cast<u32*>(sm + loff + off) = L;
            }
}
// read hi/lo buffers back in fragment layout, add into s[32]
static __device__ __forceinline__ void rb_add(const char* sm, u32 hoff, u32 loff,
                                              float* s, int RM, int CNB, int lane)
{
    const int g = lane >> 2, tg = lane & 3;
#pragma unroll
    for (int mt = 0; mt < 2; mt++)
#pragma unroll
        for (int nt = 0; nt < 4; nt++)
#pragma unroll
            for (int h = 0; h < 2; h++) {
                int r = RM + mt * 16 + g + h * 8;
                u32 off = (u32)r * 128u +
                          (((u32)(CNB + nt * 16 + tg * 4)) ^ (u32)((r & 7) << 4));
                u32 vh = *reinterpret_cast<const u32*>(sm + hoff + off);
                u32 vl = *reinterpret_cast<const u32*>(sm + loff + off);
                float2 fh = __bfloat1622float2(*reinterpret_cast<__nv_bfloat162*>(&vh));
                float2 fl = __bfloat1622float2(*reinterpret_cast<__nv_bfloat162*>(&vl));
                int i = (mt * 4 + nt) * 4 + h * 2;
                s[i]     += fh.x + fl.x;
                s[i + 1] += fh.y + fl.y;
            }
}

__global__ void __launch_bounds__(128, 3)
rede_mma(const float* __restrict__ G, float* __restrict__ O, Coefs cf)
{
    extern __shared__ __align__(128) char sm[];
    const u32 sb = s2u(sm);
    const int tid = threadIdx.x;
    const int warp = tid >> 5, lane = tid & 31;
    const int RM = (warp >> 1) * 32;        // warp row base
    const int CNB = (warp & 1) * 64;        // warp col base (bytes)
    const int g = lane >> 2, tg = lane & 3;

    const float* Gm = G + (size_t)blockIdx.x * 4096;
    float*       Om = O + (size_t)blockIdx.x * 4096;

    // ---- prologue: load M, split to bf16 hi/lo, store swizzled ----
    {
        const int row = tid >> 1;
        const int halfb = (tid & 1) * 64;
        const float* src = Gm + row * 64 + (tid & 1) * 32;
#pragma unroll
        for (int j = 0; j < 4; j++) {
            float4 a = *reinterpret_cast<const float4*>(src + j * 8);
            float4 b = *reinterpret_cast<const float4*>(src + j * 8 + 4);
            u32 h0, l0, h1, l1, h2, l2, h3, l3;
            split2(a.x, a.y, h0, l0);
            split2(a.z, a.w, h1, l1);
            split2(b.x, b.y, h2, l2);
            split2(b.z, b.w, h3, l3);
            u32 off = (u32)row * 128u +
                      ((u32)(halfb + j * 16) ^ (u32)((row & 7) << 4));
            *reinterpret_cast<uint4*>(sm + OFF_MH + off) = make_uint4(h0, h1, h2, h3);
            *reinterpret_cast<uint4*>(sm + OFF_ML + off) = make_uint4(l0, l1, l2, l3);
        }
    }
    __syncthreads();

    float E[32];

    // ---- G1: W2 = k2 * M*M ----
    {
        float acc[32];
        gemm3(acc, sb, OFF_MH, OFF_ML, OFF_MH, OFF_ML, RM, CNB, lane);
#pragma unroll
        for (int mt = 0; mt < 2; mt++)
#pragma unroll
            for (int nt = 0; nt < 4; nt++)
#pragma unroll
                for (int h = 0; h < 2; h++) {
                    int r = RM + mt * 16 + g + h * 8;
                    int c = (CNB >> 1) + nt * 8 + tg * 2;
                    int i = (mt * 4 + nt) * 4 + h * 2;
                    float x0 = cf.k2 * acc[i];
                    float x1 = cf.k2 * acc[i + 1];
                    acc[i] = x0; acc[i + 1] = x1;
                    E[i]     = ((r == c)     ? 1.f : 0.f) + cf.c3 * x0;
                    E[i + 1] = ((r == c + 1) ? 1.f : 0.f) + cf.c3 * x1;
                }
        st32(sm, OFF_W2H, OFF_W2L, acc, RM, CNB, lane);
    }
    __syncthreads();

    // ---- G2: W4 = k4 * W2*W2 ----
    {
        float acc[32];
        gemm3(acc, sb, OFF_W2H, OFF_W2L, OFF_W2H, OFF_W2L, RM, CNB, lane);
#pragma unroll
        for (int i = 0; i < 32; i++) {
            acc[i] *= cf.k4;
            E[i] += cf.c5 * acc[i];
        }
        st32(sm, OFF_XH, OFF_XL, acc, RM, CNB, lane);
    }
    __syncthreads();

    // ---- G3: W6 = k6 * W4*W2 ; S = W2 + W4 + W6 ----
    float S[32];
    {
        gemm3(S, sb, OFF_XH, OFF_XL, OFF_W2H, OFF_W2L, RM, CNB, lane);
#pragma unroll
        for (int i = 0; i < 32; i++) {
            S[i] *= cf.k6;
            E[i] += cf.c7 * S[i];
        }
        rb_add(sm, OFF_W2H, OFF_W2L, S, RM, CNB, lane);  // += W2
        rb_add(sm, OFF_XH, OFF_XL, S, RM, CNB, lane);    // += W4
    }
    __syncthreads();                    // all X(=W4)/W2 reads done
    st32(sm, OFF_XH, OFF_XL, E, RM, CNB, lane);          // X <- E
    __syncthreads();

    // ---- G4: F = M*E ; out = fs*(F + S) ----
    {
        float f[32];
        gemm3(f, sb, OFF_MH, OFF_ML, OFF_XH, OFF_XL, RM, CNB, lane);
#pragma unroll
        for (int mt = 0; mt < 2; mt++)
#pragma unroll
            for (int nt = 0; nt < 4; nt++)
#pragma unroll
                for (int h = 0; h < 2; h++) {
                    int r = RM + mt * 16 + g + h * 8;
                    int c = (CNB >> 1) + nt * 8 + tg * 2;
                    int i = (mt * 4 + nt) * 4 + h * 2;
                    float2 v;
                    v.x = cf.fs * (f[i] + S[i]);
                    v.y = cf.fs * (f[i + 1] + S[i + 1]);
                    *reinterpret_cast<float2*>(Om + r * 64 + c) = v;
                }
    }
}

extern "C" void kernel_launch(void* const* d_in, const int* in_sizes, int n_in,
                              void* d_out, int out_size)
{
    const float* M = (const float*)d_in[0];
    float* out = (float*)d_out;
    int nmat = in_sizes[0] / 4096;

    // Exact variances V_p of M^p entries at R=64 (from _D_PARMS), V_1 = 1.
    const double C2 = sqrt(64.0);
    const double C3 = sqrt(4104.0);
    const double C4 = sqrt(263696.0);
    const double C5 = sqrt(17021060.0);
    const double C6 = sqrt(1104218816.0);
    const double C7 = sqrt(72260728960.0);

    Coefs cf;
    cf.k2 = (float)(1.0 / C2);
    cf.k4 = (float)((C2 * C2) / C4);
    cf.k6 = (float)((C4 * C2) / C6);
    cf.c3 = (float)(C2 / C3);
    cf.c5 = (float)(C4 / C5);
    cf.c7 = (float)(C6 / C7);
    cf.fs = (float)(1.0 / sqrt(7.0));

    cudaFuncSetAttribute(rede_mma, cudaFuncAttributeMaxDynamicSharedMemorySize,
                         SMEM_TOTAL);
    rede_mma<<<nmat, 128, SMEM_TOTAL>>>(M, out, cf);
}

// round 6
// speedup vs baseline: 5.6621x; 1.0216x over previous
#include <cuda_runtime.h>
#include <cuda_bf16.h>
#include <math.h>
#include <stdint.h>

typedef uint32_t u32;

// out = (1/sqrt(7)) * sum_{p=1..7} M^p / sqrt(V_p)
// Horner in W2 = M^2/8 with diagonal absorption (all coefficients exact):
//   T2' = (M + a2*I) * W2 + b2*M
//   T3' = (T2' + a3*I) * W2 + b3*M
//   acc' = (T3' + a4*I) * W2 + b4*M
//   out = fo * acc'          (fo = g1*g3*g5/sqrt(7))
// GEMMs: bf16 hi/lo split, D = Ah*Bh + Al*Bh + Ah*Bl (fp32 accum), mma.m16n8k16.
// A's own K-half comes from the warp's previous accumulators (register chaining).
struct Cf { float k2, a2, b2, a3, b3, a4, b4, fo; };

#define P_AH 0u
#define P_AL 8192u
#define P_WH 16384u
#define P_WL 24576u
#define SMEM_TOTAL 32768

static __device__ __forceinline__ u32 s2u(const void* p) {
    u32 a;
    asm("{ .reg .u64 t; cvta.to.shared.u64 t, %1; cvt.u32.u64 %0, t; }"
        : "=r"(a) : "l"(p));
    return a;
}
static __device__ __forceinline__ void ldsm4(u32* r, u32 a) {
    asm volatile("ldmatrix.sync.aligned.m8n8.x4.shared.b16 {%0,%1,%2,%3},[%4];"
                 : "=r"(r[0]), "=r"(r[1]), "=r"(r[2]), "=r"(r[3]) : "r"(a));
}
static __device__ __forceinline__ void ldsm4t(u32* r, u32 a) {
    asm volatile("ldmatrix.sync.aligned.m8n8.x4.trans.shared.b16 {%0,%1,%2,%3},[%4];"
                 : "=r"(r[0]), "=r"(r[1]), "=r"(r[2]), "=r"(r[3]) : "r"(a));
}
static __device__ __forceinline__ void mma16816(float* c, const u32* a, const u32* b) {
    asm volatile(
        "mma.sync.aligned.m16n8k16.row.col.f32.bf16.bf16.f32 "
        "{%0,%1,%2,%3},{%4,%5,%6,%7},{%8,%9},{%0,%1,%2,%3};"
        : "+f"(c[0]), "+f"(c[1]), "+f"(c[2]), "+f"(c[3])
        : "r"(a[0]), "r"(a[1]), "r"(a[2]), "r"(a[3]), "r"(b[0]), "r"(b[1]));
}
static __device__ __forceinline__ void split2(float x0, float x1, u32& H, u32& L) {
    __nv_bfloat16 h0 = __float2bfloat16_rn(x0);
    __nv_bfloat16 h1 = __float2bfloat16_rn(x1);
    float r0 = x0 - __bfloat162float(h0);
    float r1 = x1 - __bfloat162float(h1);
    __nv_bfloat162 hh = __halves2bfloat162(h0, h1);
    __nv_bfloat162 ll = __halves2bfloat162(__float2bfloat16_rn(r0),
                                           __float2bfloat16_rn(r1));
    H = *reinterpret_cast<u32*>(&hh);
    L = *reinterpret_cast<u32*>(&ll);
}
static __device__ __forceinline__ float2 upk2(u32 v) {
    return __bfloat1622float2(*reinterpret_cast<__nv_bfloat162*>(&v));
}
// add alf onto the diagonal positions of an A-fragment register pair (a0 or a3)
static __device__ __forceinline__ void fixd(u32& h, u32& l, float alf, int g, int tg) {
    float2 vh = upk2(h), vl = upk2(l);
    float x0 = vh.x + vl.x + ((g == tg * 2)     ? alf : 0.f);
    float x1 = vh.y + vl.y + ((g == tg * 2 + 1) ? alf : 0.f);
    split2(x0, x1, h, l);
}

// acc[32] += A*B over K=64. Own K-half A from packed regs aph/apl; other half
// via ldmatrix from planes aplH/aplL. B from planes bplH/bplL. alf: diagonal
// bump applied to A fragments (G2 only; 0 elsewhere since baked into stores).
static __device__ __forceinline__ void gemm_h(
    float acc[32], u32 sb,
    const u32 aph[16], const u32 apl[16],
    u32 aplH, u32 aplL, u32 bplH, u32 bplL,
    int RM, int CN, int lane, float alf)
{
    const int sub = lane >> 3, l7 = lane & 7;
    const int g = lane >> 2, tg = lane & 3;
    const int CNB = CN * 2;
#pragma unroll
    for (int q = 0; q < 4; q++) {
        const int own = (q < 2);
        const int kb = q & 1;
        const int ks = own ? ((CN >> 4) + kb) : (((CN ^ 32) >> 4) + kb);
        u32 ah[8], al[8];
        if (own) {
#pragma unroll
            for (int mt = 0; mt < 2; mt++) {
                ah[mt * 4 + 0] = aph[(mt * 4 + 2 * kb) * 2 + 0];
                ah[mt * 4 + 1] = aph[(mt * 4 + 2 * kb) * 2 + 1];
                ah[mt * 4 + 2] = aph[(mt * 4 + 2 * kb + 1) * 2 + 0];
                ah[mt * 4 + 3] = aph[(mt * 4 + 2 * kb + 1) * 2 + 1];
                al[mt * 4 + 0] = apl[(mt * 4 + 2 * kb) * 2 + 0];
                al[mt * 4 + 1] = apl[(mt * 4 + 2 * kb) * 2 + 1];
                al[mt * 4 + 2] = apl[(mt * 4 + 2 * kb + 1) * 2 + 0];
                al[mt * 4 + 3] = apl[(mt * 4 + 2 * kb + 1) * 2 + 1];
            }
            if (alf != 0.f && RM == CN) {   // diag falls in own K-half, block mt==kb
                fixd(ah[kb * 4 + 0], al[kb * 4 + 0], alf, g, tg);
                fixd(ah[kb * 4 + 3], al[kb * 4 + 3], alf, g, tg);
            }
        } else {
#pragma unroll
            for (int mt = 0; mt < 2; mt++) {
                int arow = RM + mt * 16 + ((sub & 1) << 3) + l7;
                u32 ab = (u32)arow * 128u +
                         (((u32)(ks * 32 + ((sub >> 1) << 4))) ^ (u32)((arow & 7) << 4));
                ldsm4(ah + mt * 4, sb + aplH + ab);
                ldsm4(al + mt * 4, sb + aplL + ab);
            }
            if (alf != 0.f && RM == (CN ^ 32)) {  // diag in other K-half, block mt==kb
                fixd(ah[kb * 4 + 0], al[kb * 4 + 0], alf, g, tg);
                fixd(ah[kb * 4 + 3], al[kb * 4 + 3], alf, g, tg);
            }
        }
        const int krow = ks * 16 + ((sub & 1) << 3) + l7;
        const u32 kswz = (u32)((krow & 7) << 4);
        u32 bh[8], bl[8];
#pragma unroll
        for (int np = 0; np < 2; np++) {
            u32 bb = (u32)krow * 128u +
                     (((u32)(CNB + np * 32 + ((sub >> 1) << 4))) ^ kswz);
            ldsm4t(bh + np * 4, sb + bplH + bb);
            ldsm4t(bl + np * 4, sb + bplL + bb);
        }
#pragma unroll
        for (int mt = 0; mt < 2; mt++)
#pragma unroll
            for (int nt = 0; nt < 4; nt++) {
                float* c = acc + (mt * 4 + nt) * 4;
                mma16816(c, ah + mt * 4, bh + nt * 2);
                mma16816(c, al + mt * 4, bh + nt * 2);
                mma16816(c, ah + mt * 4, bl + nt * 2);
            }
    }
}

// store warp's 32x32 slab (fp32 vals -> bf16 hi/lo planes, swizzled)
static __device__ __forceinline__ void st_slab(char* sm, u32 hoff, u32 loff,
                                               const float* a, int RM, int CNB, int lane)
{
    const int g = lane >> 2, tg = lane & 3;
#pragma unroll
    for (int mt = 0; mt < 2; mt++)
#pragma unroll
        for (int nt = 0; nt < 4; nt++)
#pragma unroll
            for (int h = 0; h < 2; h++) {
                int r = RM + mt * 16 + g + h * 8;
                u32 off = (u32)r * 128u +
                          (((u32)(CNB + nt * 16 + tg * 4)) ^ (u32)((r & 7) << 4));
                u32 H, L;
                int i = (mt * 4 + nt) * 4 + h * 2;
                split2(a[i], a[i + 1], H, L);
                *reinterpret_cast<u32*>(sm + hoff + off) = H;
                *reinterpret_cast<u32*>(sm + loff + off) = L;
            }
}
// add alf to diagonal entries of acc (only warps with RM==CN hold diagonal)
static __device__ __forceinline__ void diag_add(float* acc, float alf,
                                                int RM, int CN, int lane)
{
    if (RM != CN) return;
    const int g = lane >> 2, tg = lane & 3;
#pragma unroll
    for (int mt = 0; mt < 2; mt++)
#pragma unroll
        for (int nt = 0; nt < 4; nt++)
#pragma unroll
            for (int h = 0; h < 2; h++) {
                int rr = mt * 16 + g + h * 8;
                int cc = nt * 8 + tg * 2;
                int i = (mt * 4 + nt) * 4 + h * 2;
                if (rr == cc)     acc[i]     += alf;
                if (rr == cc + 1) acc[i + 1] += alf;
            }
}
static __device__ __forceinline__ void pack32(const float* acc, u32* ph, u32* pl) {
#pragma unroll
    for (int i = 0; i < 16; i++) split2(acc[2 * i], acc[2 * i + 1], ph[i], pl[i]);
}
static __device__ __forceinline__ void init_beta(float* acc, const u32* mh,
                                                 const u32* ml, float b) {
#pragma unroll
    for (int i = 0; i < 16; i++) {
        float2 h = upk2(mh[i]), l = upk2(ml[i]);
        acc[2 * i]     = b * (h.x + l.x);
        acc[2 * i + 1] = b * (h.y + l.y);
    }
}

__global__ void __launch_bounds__(128, 3)
rede_h(const float* __restrict__ G, float* __restrict__ O, Cf cf)
{
    extern __shared__ __align__(128) char sm[];
    const u32 sb = s2u(sm);
    const int tid = threadIdx.x;
    const int warp = tid >> 5, lane = tid & 31;
    const int RM = (warp >> 1) * 32;
    const int CN = (warp & 1) * 32;
    const int CNB = CN * 2;
    const int g = lane >> 2, tg = lane & 3;

    const float* Gm = G + (size_t)blockIdx.x * 4096;
    float*       Om = O + (size_t)blockIdx.x * 4096;

    // ---- prologue: M -> bf16 hi/lo planes (swizzled) ----
    {
        const int row = tid >> 1;
        const int halfb = (tid & 1) * 64;
        const float* src = Gm + row * 64 + (tid & 1) * 32;
#pragma unroll
        for (int j = 0; j < 4; j++) {
            float4 a = *reinterpret_cast<const float4*>(src + j * 8);
            float4 b = *reinterpret_cast<const float4*>(src + j * 8 + 4);
            u32 h0, l0, h1, l1, h2, l2, h3, l3;
            split2(a.x, a.y, h0, l0);
            split2(a.z, a.w, h1, l1);
            split2(b.x, b.y, h2, l2);
            split2(b.z, b.w, h3, l3);
            u32 off = (u32)row * 128u +
                      ((u32)(halfb + j * 16) ^ (u32)((row & 7) << 4));
            *reinterpret_cast<uint4*>(sm + P_AH + off) = make_uint4(h0, h1, h2, h3);
            *reinterpret_cast<uint4*>(sm + P_AL + off) = make_uint4(l0, l1, l2, l3);
        }
    }
    // ---- M at this thread's accumulator positions, packed hi/lo ----
    u32 mh[16], ml[16];
    {
        float mv[32];
#pragma unroll
        for (int mt = 0; mt < 2; mt++)
#pragma unroll
            for (int nt = 0; nt < 4; nt++)
#pragma unroll
                for (int h = 0; h < 2; h++) {
                    int r = RM + mt * 16 + g + h * 8;
                    int c = CN + nt * 8 + tg * 2;
                    float2 v = *reinterpret_cast<const float2*>(Gm + r * 64 + c);
                    int i = (mt * 4 + nt) * 4 + h * 2;
                    mv[i] = v.x; mv[i + 1] = v.y;
                }
        pack32(mv, mh, ml);
    }
    __syncthreads();

    float acc[32];
    u32 aph[16], apl[16];

    // ---- G1: W2 = k2 * M*M ----
#pragma unroll
    for (int i = 0; i < 32; i++) acc[i] = 0.f;
    gemm_h(acc, sb, mh, ml, P_AH, P_AL, P_AH, P_AL, RM, CN, lane, 0.f);
#pragma unroll
    for (int i = 0; i < 32; i++) acc[i] *= cf.k2;
    st_slab(sm, P_WH, P_WL, acc, RM, CNB, lane);
    __syncthreads();                          // W2 visible; PA (M) untouched

    // ---- G2: T2' = (M + a2*I)*W2 + b2*M ----
    init_beta(acc, mh, ml, cf.b2);
    gemm_h(acc, sb, mh, ml, P_AH, P_AL, P_WH, P_WL, RM, CN, lane, cf.a2);
    diag_add(acc, cf.a3, RM, CN, lane);       // bake A3 = T2' + a3*I
    pack32(acc, aph, apl);
    __syncthreads();                          // all reads of PA (M) done
    st_slab(sm, P_AH, P_AL, acc, RM, CNB, lane);   // PA <- A3
    __syncthreads();

    // ---- G3: T3' = A3*W2 + b3*M ----
    init_beta(acc, mh, ml, cf.b3);
    gemm_h(acc, sb, aph, apl, P_AH, P_AL, P_WH, P_WL, RM, CN, lane, 0.f);
    diag_add(acc, cf.a4, RM, CN, lane);       // bake A4 = T3' + a4*I
    pack32(acc, aph, apl);
    __syncthreads();                          // reads of PA (A3) done
    st_slab(sm, P_AH, P_AL, acc, RM, CNB, lane);   // PA <- A4
    __syncthreads();

    // ---- G4: acc' = A4*W2 + b4*M ; out = fo * acc' ----
    init_beta(acc, mh, ml, cf.b4);
    gemm_h(acc, sb, aph, apl, P_AH, P_AL, P_WH, P_WL, RM, CN, lane, 0.f);
#pragma unroll
    for (int mt = 0; mt < 2; mt++)
#pragma unroll
        for (int nt = 0; nt < 4; nt++)
#pragma unroll
            for (int h = 0; h < 2; h++) {
                int r = RM + mt * 16 + g + h * 8;
                int c = CN + nt * 8 + tg * 2;
                int i = (mt * 4 + nt) * 4 + h * 2;
                float2 v;
                v.x = cf.fo * acc[i];
                v.y = cf.fo * acc[i + 1];
                *reinterpret_cast<float2*>(Om + r * 64 + c) = v;
            }
}

extern "C" void kernel_launch(void* const* d_in, const int* in_sizes, int n_in,
                              void* d_out, int out_size)
{
    const float* M = (const float*)d_in[0];
    float* out = (float*)d_out;
    int nmat = in_sizes[0] / 4096;

    // Exact variances V_p of M^p entries at R=64 (from _D_PARMS), V_1 = 1.
    const double V1 = 1.0, V2 = 64.0, V3 = 4104.0, V4 = 263696.0;
    const double V5 = 17021060.0, V6 = 1104218816.0, V7 = 72260728960.0;
    const double g1 = sqrt(64.0 * V1 / V3);
    const double g2 = sqrt(64.0 * V2 / V4);
    const double g3 = sqrt(64.0 * V3 / V5);
    const double g4 = sqrt(64.0 * V4 / V6);
    const double g5 = sqrt(64.0 * V5 / V7);
    const double ggg = g1 * g3 * g5;

    Cf cf;
    cf.k2 = 0.125f;                          // W2 = M*M / sqrt(V2)
    cf.a2 = (float)(g4 * g2 / ggg);
    cf.b2 = (float)(g3 * g1 / ggg);
    cf.a3 = (float)(g2 / ggg);
    cf.b3 = (float)(g1 / ggg);
    cf.a4 = (float)(1.0 / ggg);
    cf.b4 = (float)(1.0 / ggg);
    cf.fo = (float)(ggg / sqrt(7.0));

    cudaFuncSetAttribute(rede_h, cudaFuncAttributeMaxDynamicSharedMemorySize,
                         SMEM_TOTAL);
    rede_h<<<nmat, 128, SMEM_TOTAL>>>(M, out, cf);
}

// round 7
// speedup vs baseline: 5.8244x; 1.0287x over previous
#include <cuda_runtime.h>
#include <cuda_bf16.h>
#include <math.h>
#include <stdint.h>

typedef uint32_t u32;

// out = (1/sqrt(7)) * sum_{p=1..7} M^p / sqrt(V_p)
// Horner in W2 = M^2/8 with diagonal absorption (exact coefficients):
//   T2' = (M + a2*I) * W2 + b2*M
//   A3  = T2' + a3*I ;  T3' = A3*W2 + b3*M
//   A4  = T3' + a4*I ;  acc' = A4*W2 + b4*M ;  out = fo * acc'
// GEMMs: bf16 hi/lo split, D = Ah*Bh + Al*Bh + Ah*Bl (fp32 accum), mma.m16n8k16.
// Warp tile = 16 rows x 64 cols => the warp's accumulators ARE the next A
// operand (register chaining for ALL of A). B = W2 fixed after G1, so
// G2/G3/G4 run with NO barriers and NO smem stores.
struct Cf { float k2, a2, b2, a3, b3, a4, b4, fo; };

#define P_MH 0u
#define P_ML 8192u
#define P_WH 16384u
#define P_WL 24576u
#define SMEM_TOTAL 32768

static __device__ __forceinline__ u32 s2u(const void* p) {
    u32 a;
    asm("{ .reg .u64 t; cvta.to.shared.u64 t, %1; cvt.u32.u64 %0, t; }"
        : "=r"(a) : "l"(p));
    return a;
}
static __device__ __forceinline__ void ldsm4(u32* r, u32 a) {
    asm volatile("ldmatrix.sync.aligned.m8n8.x4.shared.b16 {%0,%1,%2,%3},[%4];"
                 : "=r"(r[0]), "=r"(r[1]), "=r"(r[2]), "=r"(r[3]) : "r"(a));
}
static __device__ __forceinline__ void ldsm4t(u32* r, u32 a) {
    asm volatile("ldmatrix.sync.aligned.m8n8.x4.trans.shared.b16 {%0,%1,%2,%3},[%4];"
                 : "=r"(r[0]), "=r"(r[1]), "=r"(r[2]), "=r"(r[3]) : "r"(a));
}
static __device__ __forceinline__ void mma16816(float* c, const u32* a, const u32* b) {
    asm volatile(
        "mma.sync.aligned.m16n8k16.row.col.f32.bf16.bf16.f32 "
        "{%0,%1,%2,%3},{%4,%5,%6,%7},{%8,%9},{%0,%1,%2,%3};"
        : "+f"(c[0]), "+f"(c[1]), "+f"(c[2]), "+f"(c[3])
        : "r"(a[0]), "r"(a[1]), "r"(a[2]), "r"(a[3]), "r"(b[0]), "r"(b[1]));
}
static __device__ __forceinline__ void split2(float x0, float x1, u32& H, u32& L) {
    __nv_bfloat16 h0 = __float2bfloat16_rn(x0);
    __nv_bfloat16 h1 = __float2bfloat16_rn(x1);
    float r0 = x0 - __bfloat162float(h0);
    float r1 = x1 - __bfloat162float(h1);
    __nv_bfloat162 hh = __halves2bfloat162(h0, h1);
    __nv_bfloat162 ll = __halves2bfloat162(__float2bfloat16_rn(r0),
                                           __float2bfloat16_rn(r1));
    H = *reinterpret_cast<u32*>(&hh);
    L = *reinterpret_cast<u32*>(&ll);
}
static __device__ __forceinline__ float2 upk2(u32 v) {
    return __bfloat1622float2(*reinterpret_cast<__nv_bfloat162*>(&v));
}
// add alf onto diagonal elems inside an A-fragment register pair (a0 or a3)
static __device__ __forceinline__ void fixd(u32& h, u32& l, float alf, int g, int tg) {
    float2 vh = upk2(h), vl = upk2(l);
    float x0 = vh.x + vl.x + ((g == tg * 2)     ? alf : 0.f);
    float x1 = vh.y + vl.y + ((g == tg * 2 + 1) ? alf : 0.f);
    split2(x0, x1, h, l);
}

// acc[32] += A*B over K=64, D slab = rows [RW,RW+16) x cols [0,64).
// A from packed regs (aph/apl) if non-null, else ldsm from planes aH/aL
// (with +alf on diagonal at k-step dks). B from planes bH/bL.
static __device__ __forceinline__ void gemm16(
    float acc[32], u32 sb, const u32* aph, const u32* apl,
    u32 aH, u32 aL, u32 bH, u32 bL,
    int RW, int lane, float alf, int dks)
{
    const int sub = lane >> 3, l7 = lane & 7;
    const int g = lane >> 2, tg = lane & 3;
#pragma unroll
    for (int ks = 0; ks < 4; ks++) {
        u32 ah[4], al[4];
        if (aph) {
#pragma unroll
            for (int j = 0; j < 4; j++) {
                ah[j] = aph[ks * 4 + j];
                al[j] = apl[ks * 4 + j];
            }
        } else {
            int arow = RW + ((sub & 1) << 3) + l7;
            u32 ab = (u32)arow * 128u +
                     (((u32)(ks * 32 + ((sub >> 1) << 4))) ^ (u32)((arow & 7) << 4));
            ldsm4(ah, sb + aH + ab);
            ldsm4(al, sb + aL + ab);
            if (ks == dks) {
                fixd(ah[0], al[0], alf, g, tg);
                fixd(ah[3], al[3], alf, g, tg);
            }
        }
        const int krow = ks * 16 + ((sub & 1) << 3) + l7;
        const u32 kswz = (u32)((krow & 7) << 4);
#pragma unroll
        for (int half = 0; half < 2; half++) {
            u32 bh[8], bl[8];
#pragma unroll
            for (int np = 0; np < 2; np++) {
                u32 bb = (u32)krow * 128u +
                         (((u32)((half * 2 + np) * 32 + ((sub >> 1) << 4))) ^ kswz);
                ldsm4t(bh + np * 4, sb + bH + bb);
                ldsm4t(bl + np * 4, sb + bL + bb);
            }
#pragma unroll
            for (int nt = 0; nt < 4; nt++) {
                float* c = acc + (half * 4 + nt) * 4;
                mma16816(c, ah, bh + nt * 2);
                mma16816(c, al, bh + nt * 2);
                mma16816(c, ah, bl + nt * 2);
            }
        }
    }
}

// acc = b * M (M read from hi/lo planes at fragment positions; conflict-free)
static __device__ __forceinline__ void init_beta(float acc[32], const char* sm,
                                                 float b, int RW, int g, int tg)
{
#pragma unroll
    for (int nt = 0; nt < 8; nt++)
#pragma unroll
        for (int h = 0; h < 2; h++) {
            int r = RW + g + 8 * h;
            u32 off = (u32)r * 128u +
                      (((u32)(nt * 16 + tg * 4)) ^ (u32)((r & 7) << 4));
            u32 vh = *reinterpret_cast<const u32*>(sm + P_MH + off);
            u32 vl = *reinterpret_cast<const u32*>(sm + P_ML + off);
            float2 fh = upk2(vh), fl = upk2(vl);
            acc[nt * 4 + 2 * h]     = b * (fh.x + fl.x);
            acc[nt * 4 + 2 * h + 1] = b * (fh.y + fl.y);
        }
}
// acc diagonal += alf (diag of rows [RW,RW+16) lands in n-tiles 2w, 2w+1)
static __device__ __forceinline__ void diag_add(float acc[32], float alf,
                                                int warp, int g, int tg)
{
    if (tg == (g >> 1)) {
#pragma unroll
        for (int h = 0; h < 2; h++)
            acc[(2 * warp + h) * 4 + 2 * h + (g & 1)] += alf;
    }
}
// pack accumulators -> A-fragment regs (layouts coincide: a[i] = acc[2i..2i+1])
static __device__ __forceinline__ void pack32(const float* acc, u32* ph, u32* pl) {
#pragma unroll
    for (int i = 0; i < 16; i++) split2(acc[2 * i], acc[2 * i + 1], ph[i], pl[i]);
}

__global__ void __launch_bounds__(128, 3)
rede_w(const float* __restrict__ G, float* __restrict__ O, Cf cf)
{
    extern __shared__ __align__(128) char sm[];
    const u32 sb = s2u(sm);
    const int tid = threadIdx.x;
    const int warp = tid >> 5, lane = tid & 31;
    const int RW = warp * 16;
    const int g = lane >> 2, tg = lane & 3;

    const float* Gm = G + (size_t)blockIdx.x * 4096;
    float*       Om = O + (size_t)blockIdx.x * 4096;

    // ---- prologue: M -> bf16 hi/lo planes (swizzled) ----
    {
        const int row = tid >> 1;
        const int halfb = (tid & 1) * 64;
        const float* src = Gm + row * 64 + (tid & 1) * 32;
#pragma unroll
        for (int j = 0; j < 4; j++) {
            float4 a = *reinterpret_cast<const float4*>(src + j * 8);
            float4 b = *reinterpret_cast<const float4*>(src + j * 8 + 4);
            u32 h0, l0, h1, l1, h2, l2, h3, l3;
            split2(a.x, a.y, h0, l0);
            split2(a.z, a.w, h1, l1);
            split2(b.x, b.y, h2, l2);
            split2(b.z, b.w, h3, l3);
            u32 off = (u32)row * 128u +
                      ((u32)(halfb + j * 16) ^ (u32)((row & 7) << 4));
            *reinterpret_cast<uint4*>(sm + P_MH + off) = make_uint4(h0, h1, h2, h3);
            *reinterpret_cast<uint4*>(sm + P_ML + off) = make_uint4(l0, l1, l2, l3);
        }
    }
    __syncthreads();

    float acc[32];

    // ---- G1: W2 = k2 * M*M ----
#pragma unroll
    for (int i = 0; i < 32; i++) acc[i] = 0.f;
    gemm16(acc, sb, (const u32*)0, (const u32*)0,
           P_MH, P_ML, P_MH, P_ML, RW, lane, 0.f, -1);
#pragma unroll
    for (int nt = 0; nt < 8; nt++)
#pragma unroll
        for (int h = 0; h < 2; h++) {
            int r = RW + g + 8 * h;
            u32 off = (u32)r * 128u +
                      (((u32)(nt * 16 + tg * 4)) ^ (u32)((r & 7) << 4));
            u32 H, L;
            split2(cf.k2 * acc[nt * 4 + 2 * h], cf.k2 * acc[nt * 4 + 2 * h + 1], H, L);
            *reinterpret_cast<u32*>(sm + P_WH + off) = H;
            *reinterpret_cast<u32*>(sm + P_WL + off) = L;
        }
    __syncthreads();          // W2 visible to all warps; last barrier in kernel

    u32 aph[16], apl[16];

    // ---- G2: T2' = (M + a2*I)*W2 + b2*M ----
    init_beta(acc, sm, cf.b2, RW, g, tg);
    gemm16(acc, sb, (const u32*)0, (const u32*)0,
           P_MH, P_ML, P_WH, P_WL, RW, lane, cf.a2, warp);
    diag_add(acc, cf.a3, warp, g, tg);      // bake A3 = T2' + a3*I
    pack32(acc, aph, apl);

    // ---- G3: T3' = A3*W2 + b3*M ----
    init_beta(acc, sm, cf.b3, RW, g, tg);
    gemm16(acc, sb, aph, apl, 0u, 0u, P_WH, P_WL, RW, lane, 0.f, -1);
    diag_add(acc, cf.a4, warp, g, tg);      // bake A4 = T3' + a4*I
    pack32(acc, aph, apl);

    // ---- G4: acc' = A4*W2 + b4*M ; out = fo * acc' ----
    init_beta(acc, sm, cf.b4, RW, g, tg);
    gemm16(acc, sb, aph, apl, 0u, 0u, P_WH, P_WL, RW, lane, 0.f, -1);
#pragma unroll
    for (int nt = 0; nt < 8; nt++)
#pragma unroll
        for (int h = 0; h < 2; h++) {
            int r = RW + g + 8 * h;
            int c = nt * 8 + tg * 2;
            float2 v;
            v.x = cf.fo * acc[nt * 4 + 2 * h];
            v.y = cf.fo * acc[nt * 4 + 2 * h + 1];
            *reinterpret_cast<float2*>(Om + r * 64 + c) = v;
        }
}

extern "C" void kernel_launch(void* const* d_in, const int* in_sizes, int n_in,
                              void* d_out, int out_size)
{
    const float* M = (const float*)d_in[0];
    float* out = (float*)d_out;
    int nmat = in_sizes[0] / 4096;

    // Exact variances V_p of M^p entries at R=64 (from _D_PARMS), V_1 = 1.
    const double V1 = 1.0, V2 = 64.0, V3 = 4104.0, V4 = 263696.0;
    const double V5 = 17021060.0, V6 = 1104218816.0, V7 = 72260728960.0;
    const double g1 = sqrt(64.0 * V1 / V3);
    const double g2 = sqrt(64.0 * V2 / V4);
    const double g3 = sqrt(64.0 * V3 / V5);
    const double g4 = sqrt(64.0 * V4 / V6);
    const double g5 = sqrt(64.0 * V5 / V7);
    const double ggg = g1 * g3 * g5;

    Cf cf;
    cf.k2 = 0.125f;
    cf.a2 = (float)(g4 * g2 / ggg);
    cf.b2 = (float)(g3 * g1 / ggg);
    cf.a3 = (float)(g2 / ggg);
    cf.b3 = (float)(g1 / ggg);
    cf.a4 = (float)(1.0 / ggg);
    cf.b4 = (float)(1.0 / ggg);
    cf.fo = (float)(ggg / sqrt(7.0));

    cudaFuncSetAttribute(rede_w, cudaFuncAttributeMaxDynamicSharedMemorySize,
                         SMEM_TOTAL);
    rede_w<<<nmat, 128, SMEM_TOTAL>>>(M, out, cf);
}